// round 4
// baseline (speedup 1.0000x reference)
#include <cuda_runtime.h>
#include <cuda.h>
#include <cstdint>
#include <cstdio>

// ============================================================================
// BlockCirculant == GEMM:  out = x @ M^T + bias
//   M[o,k] = W[o>>7, k>>7, (k-o)&127] * D[k]   (D folded into M)
// sm_100 (plain, no 'a' features): legacy mma.sync.m16n8k8.tf32 GEMM,
// TMA + mbarrier 5-stage pipeline, ldmatrix fragment loads.
// CTA tile 128x128x32, 8 compute warps (64x32 each) + 1 TMA producer warp.
// ============================================================================

static constexpr int DIMN    = 4096;
static constexpr int TILE_M  = 128;
static constexpr int TILE_N  = 128;
static constexpr int TILE_K  = 32;                  // 32 fp32 = 128B rows (SW128)
static constexpr int STAGES  = 5;
static constexpr int K_ITERS = DIMN / TILE_K;       // 128
static constexpr int A_BYTES = TILE_M * TILE_K * 4; // 16 KB
static constexpr int B_BYTES = TILE_N * TILE_K * 4; // 16 KB
static constexpr int STAGE_BYTES = A_BYTES + B_BYTES; // 32 KB
static constexpr int SMEM_DYN = 1024 + STAGES * STAGE_BYTES; // ~161 KB
static constexpr int MTILES  = DIMN / TILE_M;       // 32
static constexpr int NTILES  = DIMN / TILE_N;       // 32

// 64 MB scratch for the materialized circulant matrix (tf32-rounded fp32)
__device__ float g_M[(size_t)DIMN * DIMN];

// ------------------------------------------------------------ PTX helpers
__device__ __forceinline__ uint32_t smem_u32(const void* p) {
    uint32_t a;
    asm("{ .reg .u64 t; cvta.to.shared.u64 t, %1; cvt.u32.u64 %0, t; }"
        : "=r"(a) : "l"(p));
    return a;
}

__device__ __forceinline__ uint32_t elect_one() {
    uint32_t pred;
    asm volatile(
        "{\n\t.reg .pred p;\n\telect.sync _|p, 0xFFFFFFFF;\n\t"
        "selp.b32 %0, 1, 0, p;\n\t}" : "=r"(pred));
    return pred;
}

#define MBARRIER_INIT(addr, cnt) \
    asm volatile("mbarrier.init.shared.b64 [%0], %1;" \
                 :: "r"((uint32_t)(addr)), "r"((uint32_t)(cnt)) : "memory")

#define MBARRIER_ARRIVE(addr) \
    asm volatile("mbarrier.arrive.shared.b64 _, [%0];" \
                 :: "r"((uint32_t)(addr)) : "memory")

#define MBARRIER_EXPECT_TX(addr, bytes) \
    asm volatile("mbarrier.arrive.expect_tx.shared.b64 _, [%0], %1;" \
                 :: "r"((uint32_t)(addr)), "r"((uint32_t)(bytes)) : "memory")

#define MBARRIER_WAIT_PARITY(addr, parity) do {                                  \
    uint32_t _mbar = (uint32_t)(addr);                                           \
    uint32_t _par  = (uint32_t)(parity);                                         \
    uint32_t _done;                                                              \
    asm volatile(                                                                \
        "{\n\t.reg .pred p;\n\t"                                                 \
        "mbarrier.try_wait.parity.acquire.cta.shared::cta.b64 p, [%1], %2;\n\t"  \
        "selp.b32 %0, 1, 0, p;\n\t}"                                             \
        : "=r"(_done) : "r"(_mbar), "r"(_par) : "memory");                       \
    if (!_done) {                                                                \
        asm volatile(                                                            \
            "{\n\t.reg .pred P1;\n\t"                                            \
            "WAIT_LOOP_%=:\n\t"                                                  \
            "mbarrier.try_wait.parity.acquire.cta.shared::cta.b64 P1, [%0], %1, 0x989680;\n\t" \
            "@P1 bra.uni WAIT_DONE_%=;\n\t"                                      \
            "bra.uni WAIT_LOOP_%=;\n\t"                                          \
            "WAIT_DONE_%=:\n\t}"                                                 \
            :: "r"(_mbar), "r"(_par) : "memory");                                \
    }                                                                            \
} while (0)

#define TMA_LOAD_2D(smem_addr, tmap, cx, cy, mbar)                               \
    asm volatile(                                                                \
        "cp.async.bulk.tensor.2d.shared::cta.global.tile.mbarrier::complete_tx::bytes " \
        "[%0], [%1, {%2, %3}], [%4];"                                            \
        :: "r"((uint32_t)(smem_addr)), "l"(tmap),                                \
           "r"((int32_t)(cx)), "r"((int32_t)(cy)),                               \
           "r"((uint32_t)(mbar)) : "memory")

#define LDSM_X4(d0, d1, d2, d3, addr)                                            \
    asm volatile("ldmatrix.sync.aligned.m8n8.x4.shared.b16 {%0,%1,%2,%3}, [%4];" \
                 : "=r"(d0), "=r"(d1), "=r"(d2), "=r"(d3) : "r"(addr))

__device__ __forceinline__ void mma_tf32(float* c, const uint32_t* a,
                                         const uint32_t* b) {
    asm volatile(
        "mma.sync.aligned.m16n8k8.row.col.f32.tf32.tf32.f32 "
        "{%0,%1,%2,%3}, {%4,%5,%6,%7}, {%8,%9}, {%0,%1,%2,%3};"
        : "+f"(c[0]), "+f"(c[1]), "+f"(c[2]), "+f"(c[3])
        : "r"(a[0]), "r"(a[1]), "r"(a[2]), "r"(a[3]), "r"(b[0]), "r"(b[1]));
}

// ------------------------------------------------------------ prep kernel
// M[o,k] = W[o>>7, k>>7, (k-o)&127] * D[k], rounded to tf32 (rna)
__global__ void bc_build_M(const float* __restrict__ W,
                           const float* __restrict__ Dvec) {
    int idx = blockIdx.x * blockDim.x + threadIdx.x;   // 0 .. 16M-1
    int k = idx & (DIMN - 1);
    int o = idx >> 12;
    int i = o >> 7;
    int j = k >> 7;
    int s = (k - o) & 127;
    float v = W[(i * 32 + j) * 128 + s] * Dvec[k];
    uint32_t u;
    asm("cvt.rna.tf32.f32 %0, %1;" : "=r"(u) : "f"(v));   // tf32 lives in b32
    g_M[idx] = __uint_as_float(u);
}

// ------------------------------------------------------------ GEMM kernel
// 288 threads: warps 0-7 compute (2M x 4N, warp tile 64x32), warp 8 TMA.
__global__ void __launch_bounds__(288, 1)
bc_gemm(const __grid_constant__ CUtensorMap tma_a,
        const __grid_constant__ CUtensorMap tma_b,
        const float* __restrict__ bias,
        float* __restrict__ out) {
    extern __shared__ char smem[];
    const uint32_t raw = smem_u32(smem);
    // Layout: [raw, raw+1024) barriers, stage tiles at 1024B alignment after.
    const uint32_t bar_full  = ((raw + 15u) & ~7u);
    const uint32_t bar_empty = bar_full + 8 * STAGES;
    const uint32_t tiles     = (raw + 1024u + 1023u) & ~1023u;

    const int tid  = threadIdx.x;
    const int wid  = tid >> 5;
    const int lane = tid & 31;

    // grouped rasterization for L2 reuse: groups of 8 M-tiles x all N-tiles
    const int bid = blockIdx.x;
    constexpr int GM = 8;
    const int grp = bid / (GM * NTILES);
    const int rem = bid % (GM * NTILES);
    const int mt  = grp * GM + (rem % GM);
    const int nt  = rem / GM;

    if (tid == 0) {
        for (int s = 0; s < STAGES; s++) {
            MBARRIER_INIT(bar_full + 8 * s, 1);    // tx-based
            MBARRIER_INIT(bar_empty + 8 * s, 8);   // one arrive per compute warp
        }
        asm volatile("fence.proxy.async.shared::cta;" ::: "memory");
    }
    __syncthreads();

    if (wid == 8) {
        // ---------------- TMA producer warp ----------------
        if (elect_one()) {
            int stage = 0, phase = 1;   // parity 1: first STAGES empty-waits pass
            for (int kt = 0; kt < K_ITERS; kt++) {
                MBARRIER_WAIT_PARITY(bar_empty + 8 * stage, phase);
                MBARRIER_EXPECT_TX(bar_full + 8 * stage, STAGE_BYTES);
                uint32_t dst = tiles + stage * STAGE_BYTES;
                TMA_LOAD_2D(dst,           &tma_a, kt * TILE_K, mt * TILE_M, bar_full + 8 * stage);
                TMA_LOAD_2D(dst + A_BYTES, &tma_b, kt * TILE_K, nt * TILE_N, bar_full + 8 * stage);
                if (++stage == STAGES) { stage = 0; phase ^= 1; }
            }
        }
        return;
    }

    // ---------------- compute warps (0-7) ----------------
    const int wm = wid & 1;          // 2 warp rows in M
    const int wn = wid >> 1;         // 4 warp cols in N
    const int mo = wm * 64;          // warp M offset within CTA tile
    const int no = wn * 32;          // warp N offset within CTA tile

    // Precompute per-lane ldmatrix offsets (SW128 swizzle: 16B chunk ^= row&7).
    // A fragment (m16k8): x4 tiles = [rows +0..7 | +8..15] x [k 0-3 | k 4-7]
    // B fragments (two n8 tiles per x4): [n 0-7, k0-3 | n 0-7, k4-7 | n 8-15, ...]
    uint32_t offA[4][4], offB[2][4];
    {
        const int t = lane >> 3, r = lane & 7;
#pragma unroll
        for (int i = 0; i < 4; i++)
#pragma unroll
            for (int ks = 0; ks < 4; ks++) {
                int row = mo + i * 16 + (t & 1) * 8 + r;
                int chunk = ks * 2 + (t >> 1);
                offA[i][ks] = row * 128 + ((chunk ^ (row & 7)) << 4);
            }
#pragma unroll
        for (int p = 0; p < 2; p++)
#pragma unroll
            for (int ks = 0; ks < 4; ks++) {
                int row = no + p * 16 + (t >> 1) * 8 + r;
                int chunk = ks * 2 + (t & 1);
                offB[p][ks] = row * 128 + ((chunk ^ (row & 7)) << 4);
            }
    }

    float c[4][4][4];
#pragma unroll
    for (int i = 0; i < 4; i++)
#pragma unroll
        for (int j = 0; j < 4; j++)
#pragma unroll
            for (int q = 0; q < 4; q++) c[i][j][q] = 0.0f;

    int stage = 0, phase = 0;
#pragma unroll 1
    for (int kt = 0; kt < K_ITERS; kt++) {
        MBARRIER_WAIT_PARITY(bar_full + 8 * stage, phase);
        const uint32_t sa = tiles + stage * STAGE_BYTES;
        const uint32_t sb = sa + A_BYTES;

#pragma unroll
        for (int ks = 0; ks < 4; ks++) {
            uint32_t a[4][4], b[4][2];
#pragma unroll
            for (int i = 0; i < 4; i++)
                LDSM_X4(a[i][0], a[i][1], a[i][2], a[i][3], sa + offA[i][ks]);
            LDSM_X4(b[0][0], b[0][1], b[1][0], b[1][1], sb + offB[0][ks]);
            LDSM_X4(b[2][0], b[2][1], b[3][0], b[3][1], sb + offB[1][ks]);
#pragma unroll
            for (int i = 0; i < 4; i++)
#pragma unroll
                for (int j = 0; j < 4; j++)
                    mma_tf32(c[i][j], a[i], b[j]);
        }
        if (elect_one()) MBARRIER_ARRIVE(bar_empty + 8 * stage);
        if (++stage == STAGES) { stage = 0; phase ^= 1; }
    }

    // ---------------- epilogue: bias add + store ----------------
    const int grow0 = mt * TILE_M + mo;
    const int gcol0 = nt * TILE_N + no;
    const int g   = lane >> 2;
    const int tig = lane & 3;
#pragma unroll
    for (int i = 0; i < 4; i++) {
        const int r0 = grow0 + i * 16 + g;
        const int r1 = r0 + 8;
        float* out0 = out + (size_t)r0 * DIMN;
        float* out1 = out + (size_t)r1 * DIMN;
#pragma unroll
        for (int j = 0; j < 4; j++) {
            const int col = gcol0 + j * 8 + tig * 2;
            const float2 bz = *reinterpret_cast<const float2*>(bias + col);
            float2 v0 = {c[i][j][0] + bz.x, c[i][j][1] + bz.y};
            float2 v1 = {c[i][j][2] + bz.x, c[i][j][3] + bz.y};
            *reinterpret_cast<float2*>(out0 + col) = v0;
            *reinterpret_cast<float2*>(out1 + col) = v1;
        }
    }
}

// ------------------------------------------------------------ host launch
extern "C" void kernel_launch(void* const* d_in, const int* in_sizes, int n_in,
                              void* d_out, int out_size) {
    const float* x    = (const float*)d_in[0];
    const float* W    = (const float*)d_in[1];
    const float* Dv   = (const float*)d_in[2];
    const float* bias = (const float*)d_in[3];
    float* out        = (float*)d_out;

    void* m_ptr = nullptr;
    cudaGetSymbolAddress(&m_ptr, g_M);

    // cuTensorMapEncodeTiled via driver entry point (no -lcuda needed)
    typedef CUresult (*EncodeFn)(CUtensorMap*, CUtensorMapDataType, cuuint32_t, void*,
                                 const cuuint64_t*, const cuuint64_t*, const cuuint32_t*,
                                 const cuuint32_t*, CUtensorMapInterleave, CUtensorMapSwizzle,
                                 CUtensorMapL2promotion, CUtensorMapFloatOOBfill);
    void* fn = nullptr;
    cudaDriverEntryPointQueryResult qr;
    cudaGetDriverEntryPoint("cuTensorMapEncodeTiled", &fn, cudaEnableDefault, &qr);
    EncodeFn encode = (EncodeFn)fn;
    if (!encode) { fprintf(stderr, "no cuTensorMapEncodeTiled\n"); return; }

    cuuint64_t dims[2]    = {(cuuint64_t)DIMN, (cuuint64_t)DIMN};
    cuuint64_t strides[1] = {(cuuint64_t)DIMN * sizeof(float)};
    cuuint32_t es[2]      = {1, 1};

    CUtensorMap ta{}, tb{};
    cuuint32_t boxA[2] = {TILE_K, TILE_M};   // 128B x 128 rows
    cuuint32_t boxB[2] = {TILE_K, TILE_N};   // 128B x 128 rows
    encode(&ta, CU_TENSOR_MAP_DATA_TYPE_FLOAT32, 2, (void*)x, dims, strides, boxA, es,
           CU_TENSOR_MAP_INTERLEAVE_NONE, CU_TENSOR_MAP_SWIZZLE_128B,
           CU_TENSOR_MAP_L2_PROMOTION_L2_128B, CU_TENSOR_MAP_FLOAT_OOB_FILL_NONE);
    encode(&tb, CU_TENSOR_MAP_DATA_TYPE_FLOAT32, 2, m_ptr, dims, strides, boxB, es,
           CU_TENSOR_MAP_INTERLEAVE_NONE, CU_TENSOR_MAP_SWIZZLE_128B,
           CU_TENSOR_MAP_L2_PROMOTION_L2_128B, CU_TENSOR_MAP_FLOAT_OOB_FILL_NONE);

    cudaFuncSetAttribute(bc_gemm, cudaFuncAttributeMaxDynamicSharedMemorySize, SMEM_DYN);

    bc_build_M<<<(DIMN * DIMN) / 256, 256>>>(W, Dv);
    bc_gemm<<<MTILES * NTILES, 288, SMEM_DYN>>>(ta, tb, bias, out);
}